// round 10
// baseline (speedup 1.0000x reference)
#include <cuda_runtime.h>
#include <cuda_bf16.h>
#include <cstdint>

// Problem constants
static constexpr int kS    = 256;
static constexpr int kB    = 16;
static constexpr int kV    = 32000;
static constexpr int kEMB  = 32;
static constexpr int kHID  = 16;
static constexpr int kG    = 4 * kHID;     // 64 gates
static constexpr int kRows = kS * kB;      // 4096
static constexpr int kMT   = 128;          // rows per m tile
static constexpr int kNT   = 128;          // cols per CTA (n tile)
static constexpr int kNTiles = kV / kNT;   // 250
static constexpr int kMTiles = kRows / kMT; // 32
static constexpr int kMLoop = 4;           // m tiles per CTA (B reuse)
static constexpr int kYBlk  = kMTiles / kMLoop;  // 8 y-blocks total
static constexpr int kFS   = 24;           // u32 row stride (conflict-free)

static constexpr float kLOG2E = 1.4426950408889634f;

// Scratch (static __device__ — no allocations allowed)
__device__ float g_gx[kS * kB * kG];
__device__ float g_concat[kRows * 2 * kHID];          // A matrix [4096][32]
__device__ float g_part[kNTiles * kRows];             // per-(ntile,row) exp-sums
__device__ float g_lz[kRows];                         // per-row logZ

__device__ __forceinline__ float sigf(float x) {
    return 1.0f / (1.0f + __expf(-x));
}
__device__ __forceinline__ float tanhfast(float x) {
    return 2.0f / (1.0f + __expf(-2.0f * x)) - 1.0f;
}
__device__ __forceinline__ float ex2f(float x) {
    float y;
    asm("ex2.approx.ftz.f32 %0, %1;" : "=f"(y) : "f"(x));
    return y;
}
__device__ __forceinline__ uint32_t pack_bf16(float lo, float hi) {
    __nv_bfloat162 h = __floats2bfloat162_rn(lo, hi);
    return *reinterpret_cast<uint32_t*>(&h);
}
// m16n8k16 bf16 MMA, fp32 accumulate
__device__ __forceinline__ void mma_bf16(float c[4], uint32_t a0, uint32_t a1,
                                         uint32_t a2, uint32_t a3,
                                         uint32_t b0, uint32_t b1) {
    asm("mma.sync.aligned.m16n8k16.row.col.f32.bf16.bf16.f32 "
        "{%0,%1,%2,%3}, {%4,%5,%6,%7}, {%8,%9}, {%0,%1,%2,%3};"
        : "+f"(c[0]), "+f"(c[1]), "+f"(c[2]), "+f"(c[3])
        : "r"(a0), "r"(a1), "r"(a2), "r"(a3), "r"(b0), "r"(b1));
}

// ---------------------------------------------------------------------------
// Kernel 0: Gx = x@W_ih.T + b_ih + b_hh (shared by both scan directions)
// ---------------------------------------------------------------------------
__global__ void gx_kernel(const int* __restrict__ tokens,
                          const float* __restrict__ emb,
                          const float* __restrict__ W_ih,
                          const float* __restrict__ b_ih,
                          const float* __restrict__ b_hh) {
    __shared__ float ws[kG * 33];
    __shared__ float xs[4][32];
    __shared__ float bb[kG];

    int tid = threadIdx.x;
    for (int i = tid; i < kG * kEMB; i += 256)
        ws[(i >> 5) * 33 + (i & 31)] = W_ih[i];
    if (tid < kG) bb[tid] = b_ih[tid] + b_hh[tid];

    int sb0 = blockIdx.x * 4;
    if (tid < 128) {
        int g = tid >> 5, k = tid & 31;
        xs[g][k] = emb[(size_t)tokens[sb0 + g] * kEMB + k];
    }
    __syncthreads();

    int g = tid >> 6;
    int j = tid & (kG - 1);
    const float* wr = ws + j * 33;
    float a0 = bb[j], a1 = 0.f, a2 = 0.f, a3 = 0.f;
#pragma unroll
    for (int k = 0; k < kEMB; k += 4) {
        a0 += xs[g][k + 0] * wr[k + 0];
        a1 += xs[g][k + 1] * wr[k + 1];
        a2 += xs[g][k + 2] * wr[k + 2];
        a3 += xs[g][k + 3] * wr[k + 3];
    }
    g_gx[(sb0 + g) * kG + j] = (a0 + a1) + (a2 + a3);
}

// ---------------------------------------------------------------------------
// Kernel 1: LSTM recurrence. 32 blocks = (2 dirs) x (16 batch lanes).
// ---------------------------------------------------------------------------
__global__ void lstm_kernel(const float* __restrict__ W_hh,
                            const float* __restrict__ init_h,
                            const float* __restrict__ init_c) {
    int dir = blockIdx.x >> 4;
    int b   = blockIdx.x & 15;
    int j   = threadIdx.x;

    __shared__ float h_sh[kHID];
    __shared__ float gact[kG];

    float w[kHID];
#pragma unroll
    for (int k = 0; k < kHID; ++k) w[k] = W_hh[j * kHID + k];

    float c_reg = 0.f, h_reg = 0.f;
    if (j < kHID) {
        h_reg = init_h[j];
        c_reg = init_c[j];
        h_sh[j] = h_reg;
    }
    __syncthreads();

    int p  = dir ? (kS - 1) : 0;
    int dp = dir ? -1 : 1;
    float gx_next = g_gx[(p * kB + b) * kG + j];

    for (int step = 0; step < kS; ++step, p += dp) {
        float gxv = gx_next;
        if (step < kS - 1) gx_next = g_gx[((p + dp) * kB + b) * kG + j];

        if (j < kHID)
            g_concat[(p * kB + b) * (2 * kHID) + dir * kHID + j] = h_reg;

        float a0 = 0.f, a1 = 0.f, a2 = 0.f, a3 = 0.f;
#pragma unroll
        for (int k = 0; k < kHID; k += 4) {
            a0 += w[k + 0] * h_sh[k + 0];
            a1 += w[k + 1] * h_sh[k + 1];
            a2 += w[k + 2] * h_sh[k + 2];
            a3 += w[k + 3] * h_sh[k + 3];
        }
        float pre = gxv + ((a0 + a1) + (a2 + a3));
        gact[j] = (j >= 32 && j < 48) ? tanhfast(pre) : sigf(pre);
        __syncthreads();

        if (j < kHID) {
            float ig = gact[j];
            float fg = gact[kHID + j];
            float gg = gact[2 * kHID + j];
            float og = gact[3 * kHID + j];
            c_reg = fg * c_reg + ig * gg;
            h_reg = og * tanhfast(c_reg);
            h_sh[j] = h_reg;
        }
        __syncthreads();
    }
}

// ---------------------------------------------------------------------------
// bf16 fragment-order staging (k-pair p of row r at column
// 2*(p&3) + ((p>>2)&1) + (p>>3)*8, row stride kFS=24 u32; operand fetches
// are single conflict-free LDS.64s).
// ---------------------------------------------------------------------------
__device__ __forceinline__ int fragcol(int p) {
    return 2 * (p & 3) + ((p >> 2) & 1) + (p >> 3) * 8;
}
__device__ __forceinline__ void stage_bf16(uint32_t* dst, const float4* src,
                                           int rows, int tid, float scale) {
    for (int i = tid; i < rows * 8; i += 256) {
        float4 v = src[i];
        int r = i >> 3, j = i & 7;           // float4 j covers k = 4j..4j+3
        dst[r * kFS + fragcol(2 * j)]     = pack_bf16(v.x * scale, v.y * scale);
        dst[r * kFS + fragcol(2 * j + 1)] = pack_bf16(v.z * scale, v.w * scale);
    }
}

// ---------------------------------------------------------------------------
// Kernel 2: bf16 tensor-core logits GEMM (two template passes), with a
// y-base offset so M-halves can be scheduled on different streams.
// Pass 1 (WRITE=false): A,bias pre-scaled by log2(e); MMA -> sum of
//   ex2.approx -> g_part[ntile][row].
// Pass 2 (WRITE=true):  MMA with acc init = b_out - logZ -> direct fragment
//   streaming stores.
// ---------------------------------------------------------------------------
template <bool WRITE>
__global__ void __launch_bounds__(256, 2)
mma_pass(const float* __restrict__ W_out,
         const float* __restrict__ b_out,
         float* __restrict__ out,
         int ybase) {
    __shared__ uint32_t A_sm[kMT * kFS];   // bf16x2 fragment order
    __shared__ uint32_t B_sm[kNT * kFS];
    __shared__ float bias_sm[kNT];
    __shared__ float lz_sm[kMT];

    int tid  = threadIdx.x;
    int warp = tid >> 5;
    int lane = tid & 31;
    int tg   = lane & 3;     // threadID-in-group
    int gr   = lane >> 2;    // groupID
    int n0   = blockIdx.x * kNT;
    int mrow = warp * 16;

    // stage B (W_out rows n0..n0+127) once
    stage_bf16(B_sm, reinterpret_cast<const float4*>(W_out + (size_t)n0 * 32),
               kNT, tid, 1.0f);
    if (tid < kNT) bias_sm[tid] = WRITE ? b_out[n0 + tid]
                                        : b_out[n0 + tid] * kLOG2E;

    for (int mi = 0; mi < kMLoop; ++mi) {
        int row0 = ((ybase + blockIdx.y) * kMLoop + mi) * kMT;

        __syncthreads();  // prev-iter A readers done / B visible on mi==0
        stage_bf16(A_sm,
                   reinterpret_cast<const float4*>(g_concat + (size_t)row0 * 32),
                   kMT, tid, WRITE ? 1.0f : kLOG2E);
        if (WRITE && tid < kMT) lz_sm[tid] = g_lz[row0 + tid];
        __syncthreads();

        // accumulators: 16 n-frags x 4
        float c[16][4];
#pragma unroll
        for (int f = 0; f < 16; ++f) {
            float bx = bias_sm[f * 8 + tg * 2];
            float by = bias_sm[f * 8 + tg * 2 + 1];
            if (WRITE) {
                float z0 = lz_sm[mrow + gr];
                float z1 = lz_sm[mrow + gr + 8];
                c[f][0] = bx - z0; c[f][1] = by - z0;
                c[f][2] = bx - z1; c[f][3] = by - z1;
            } else {
                c[f][0] = bx; c[f][1] = by;
                c[f][2] = bx; c[f][3] = by;
            }
        }

        // A fragments for this warp's two row groups
        const uint32_t* ar0 = A_sm + (mrow + gr) * kFS + tg * 2;
        const uint32_t* ar1 = A_sm + (mrow + gr + 8) * kFS + tg * 2;
        uint2 alo0 = *reinterpret_cast<const uint2*>(ar0);      // a0,a2 k0-15
        uint2 alo1 = *reinterpret_cast<const uint2*>(ar1);      // a1,a3 k0-15
        uint2 ahi0 = *reinterpret_cast<const uint2*>(ar0 + 8);  // k16-31
        uint2 ahi1 = *reinterpret_cast<const uint2*>(ar1 + 8);
        const uint32_t* bp = B_sm + gr * kFS + tg * 2;

#pragma unroll
        for (int f = 0; f < 16; ++f) {
            uint2 blo = *reinterpret_cast<const uint2*>(bp + f * 8 * kFS);
            uint2 bhi = *reinterpret_cast<const uint2*>(bp + f * 8 * kFS + 8);
            mma_bf16(c[f], alo0.x, alo1.x, alo0.y, alo1.y, blo.x, blo.y);
            mma_bf16(c[f], ahi0.x, ahi1.x, ahi0.y, ahi1.y, bhi.x, bhi.y);
        }

        if (!WRITE) {
            // per-row sum(2^logit2) = sum(exp(logit)); rows mrow+gr, +8
            float s0 = 0.f, s1 = 0.f;
#pragma unroll
            for (int f = 0; f < 16; ++f) {
                s0 += ex2f(c[f][0]) + ex2f(c[f][1]);
                s1 += ex2f(c[f][2]) + ex2f(c[f][3]);
            }
            s0 += __shfl_xor_sync(0xffffffffu, s0, 1);
            s0 += __shfl_xor_sync(0xffffffffu, s0, 2);
            s1 += __shfl_xor_sync(0xffffffffu, s1, 1);
            s1 += __shfl_xor_sync(0xffffffffu, s1, 2);
            if (tg == 0) {
                g_part[(size_t)blockIdx.x * kRows + row0 + mrow + gr]     = s0;
                g_part[(size_t)blockIdx.x * kRows + row0 + mrow + gr + 8] = s1;
            }
        } else {
            // direct fragment streaming stores (32B-aligned STG.64)
            float* orow0 = out + (size_t)(row0 + mrow + gr) * kV + n0 + tg * 2;
            float* orow1 = orow0 + (size_t)8 * kV;
#pragma unroll
            for (int f = 0; f < 16; ++f) {
                __stcs(reinterpret_cast<float2*>(orow0 + f * 8),
                       make_float2(c[f][0], c[f][1]));
                __stcs(reinterpret_cast<float2*>(orow1 + f * 8),
                       make_float2(c[f][2], c[f][3]));
            }
        }
    }
}

// ---------------------------------------------------------------------------
// Kernel 3: logZ reduce over one M-half. grid.x blocks x 256 threads =
// 32 rows x 8 t-slices each; deterministic fixed-order combine.
// ---------------------------------------------------------------------------
__global__ void logz_kernel(int rowbase) {
    __shared__ float red[8][32];
    int rl    = threadIdx.x & 31;
    int slice = threadIdx.x >> 5;
    int row   = rowbase + blockIdx.x * 32 + rl;

    float s = 0.f;
#pragma unroll 4
    for (int t = slice; t < kNTiles; t += 8)
        s += g_part[(size_t)t * kRows + row];
    red[slice][rl] = s;
    __syncthreads();

    if (slice == 0) {
        float tot = 0.f;
#pragma unroll
        for (int i = 0; i < 8; ++i) tot += red[i][rl];
        g_lz[row] = __logf(tot);
    }
}

// ---------------------------------------------------------------------------
// Fork-join schedule: overlap pass2(h0) (HBM-store-bound) with pass1(h1)
// (compute-bound) on a side stream.
// ---------------------------------------------------------------------------
extern "C" void kernel_launch(void* const* d_in, const int* in_sizes, int n_in,
                              void* d_out, int out_size) {
    const int*   tokens = (const int*)d_in[0];
    const float* emb    = (const float*)d_in[1];
    const float* W_ih   = (const float*)d_in[2];
    const float* W_hh   = (const float*)d_in[3];
    const float* b_ih   = (const float*)d_in[4];
    const float* b_hh   = (const float*)d_in[5];
    const float* W_out  = (const float*)d_in[6];
    const float* b_out  = (const float*)d_in[7];
    const float* init_h = (const float*)d_in[8];
    const float* init_c = (const float*)d_in[9];
    float* out = (float*)d_out;

    static cudaStream_t s1 = nullptr;
    static cudaEvent_t evFork = nullptr, evJoin = nullptr;
    if (s1 == nullptr) {
        cudaStreamCreateWithFlags(&s1, cudaStreamNonBlocking);
        cudaEventCreateWithFlags(&evFork, cudaEventDisableTiming);
        cudaEventCreateWithFlags(&evJoin, cudaEventDisableTiming);
    }

    constexpr int kHalfY = kYBlk / 2;          // 4 y-blocks per half
    constexpr int kHalfRows = kRows / 2;       // 2048 rows per half
    dim3 gridHalf(kNTiles, kHalfY);

    // s0 (capture/default stream): prologue + half-0 sums
    gx_kernel<<<(kS * kB) / 4, 256>>>(tokens, emb, W_ih, b_ih, b_hh);
    lstm_kernel<<<32, 64>>>(W_hh, init_h, init_c);
    mma_pass<false><<<gridHalf, 256>>>(W_out, b_out, out, 0);
    cudaEventRecord(evFork, 0);

    // s0 continues: half-1 sums (compute-bound) ...
    mma_pass<false><<<gridHalf, 256>>>(W_out, b_out, out, kHalfY);

    // ... while s1 finalizes half-0 (store-bound) concurrently
    cudaStreamWaitEvent(s1, evFork, 0);
    logz_kernel<<<kHalfRows / 32, 256, 0, s1>>>(0);
    mma_pass<true><<<gridHalf, 256, 0, s1>>>(W_out, b_out, out, 0);
    cudaEventRecord(evJoin, s1);

    // s0: finalize half-1, then join s1
    logz_kernel<<<kHalfRows / 32, 256>>>(kHalfRows);
    mma_pass<true><<<gridHalf, 256>>>(W_out, b_out, out, kHalfY);
    cudaStreamWaitEvent(0, evJoin, 0);
}

// round 11
// speedup vs baseline: 1.1516x; 1.1516x over previous
#include <cuda_runtime.h>
#include <cuda_bf16.h>
#include <cstdint>

// Problem constants
static constexpr int kS    = 256;
static constexpr int kB    = 16;
static constexpr int kV    = 32000;
static constexpr int kEMB  = 32;
static constexpr int kHID  = 16;
static constexpr int kG    = 4 * kHID;     // 64 gates
static constexpr int kRows = kS * kB;      // 4096
static constexpr int kMT   = 128;          // rows per m tile
static constexpr int kNT   = 128;          // cols per CTA (n tile)
static constexpr int kNTiles = kV / kNT;   // 250
static constexpr int kMTiles = kRows / kMT; // 32
static constexpr int kMLoop = 4;           // m tiles per CTA
static constexpr int kYBlk  = kMTiles / kMLoop;  // 8
static constexpr int kFS   = 24;           // u32 row stride (conflict-free LDS)
static constexpr int kTileU32 = kMT * kFS; // 3072 u32 = 12KB per tile

static constexpr float kLOG2E = 1.4426950408889634f;

// dynamic smem: A[4] tiles + B tile + bias + lz
static constexpr int kSmemBytes =
    (4 * kTileU32 + kTileU32) * 4 + kNT * 4 + kMLoop * kMT * 4;  // 64 KB

// Scratch (static __device__ — no allocations allowed)
__device__ float    g_gx[kS * kB * kG];
__device__ float    g_concat[kRows * 2 * kHID];   // A matrix [4096][32] f32
__device__ uint32_t g_abf1[kRows * kFS];          // A bf16-frag, x log2(e)
__device__ uint32_t g_abf2[kRows * kFS];          // A bf16-frag, plain
__device__ uint32_t g_bbf[kV * kFS];              // W_out bf16-frag (3 MB)
__device__ float    g_part[kNTiles * kRows];      // per-(ntile,row) exp-sums
__device__ float    g_lz[kRows];                  // per-row logZ

__device__ __forceinline__ float sigf(float x) {
    return 1.0f / (1.0f + __expf(-x));
}
__device__ __forceinline__ float tanhfast(float x) {
    return 2.0f / (1.0f + __expf(-2.0f * x)) - 1.0f;
}
__device__ __forceinline__ float ex2f(float x) {
    float y;
    asm("ex2.approx.ftz.f32 %0, %1;" : "=f"(y) : "f"(x));
    return y;
}
__device__ __forceinline__ uint32_t pack_bf16(float lo, float hi) {
    __nv_bfloat162 h = __floats2bfloat162_rn(lo, hi);
    return *reinterpret_cast<uint32_t*>(&h);
}
__device__ __forceinline__ void mma_bf16(float c[4], uint32_t a0, uint32_t a1,
                                         uint32_t a2, uint32_t a3,
                                         uint32_t b0, uint32_t b1) {
    asm("mma.sync.aligned.m16n8k16.row.col.f32.bf16.bf16.f32 "
        "{%0,%1,%2,%3}, {%4,%5,%6,%7}, {%8,%9}, {%0,%1,%2,%3};"
        : "+f"(c[0]), "+f"(c[1]), "+f"(c[2]), "+f"(c[3])
        : "r"(a0), "r"(a1), "r"(a2), "r"(a3), "r"(b0), "r"(b1));
}
__device__ __forceinline__ void cp16(uint32_t sdst, const void* gsrc) {
    asm volatile("cp.async.cg.shared.global [%0], [%1], 16;"
                 :: "r"(sdst), "l"(gsrc));
}
#define CP_COMMIT() asm volatile("cp.async.commit_group;")
#define CP_WAIT(N)  asm volatile("cp.async.wait_group %0;" :: "n"(N))

// fragment column for k-pair p (p = k/2, 0..15)
__device__ __forceinline__ int fragcol(int p) {
    return 2 * (p & 3) + ((p >> 2) & 1) + (p >> 3) * 8;
}

// ---------------------------------------------------------------------------
// Kernel 0: Gx = x@W_ih.T + b_ih + b_hh (shared by both scan directions)
// ---------------------------------------------------------------------------
__global__ void gx_kernel(const int* __restrict__ tokens,
                          const float* __restrict__ emb,
                          const float* __restrict__ W_ih,
                          const float* __restrict__ b_ih,
                          const float* __restrict__ b_hh) {
    __shared__ float ws[kG * 33];
    __shared__ float xs[4][32];
    __shared__ float bb[kG];

    int tid = threadIdx.x;
    for (int i = tid; i < kG * kEMB; i += 256)
        ws[(i >> 5) * 33 + (i & 31)] = W_ih[i];
    if (tid < kG) bb[tid] = b_ih[tid] + b_hh[tid];

    int sb0 = blockIdx.x * 4;
    if (tid < 128) {
        int g = tid >> 5, k = tid & 31;
        xs[g][k] = emb[(size_t)tokens[sb0 + g] * kEMB + k];
    }
    __syncthreads();

    int g = tid >> 6;
    int j = tid & (kG - 1);
    const float* wr = ws + j * 33;
    float a0 = bb[j], a1 = 0.f, a2 = 0.f, a3 = 0.f;
#pragma unroll
    for (int k = 0; k < kEMB; k += 4) {
        a0 += xs[g][k + 0] * wr[k + 0];
        a1 += xs[g][k + 1] * wr[k + 1];
        a2 += xs[g][k + 2] * wr[k + 2];
        a3 += xs[g][k + 3] * wr[k + 3];
    }
    g_gx[(sb0 + g) * kG + j] = (a0 + a1) + (a2 + a3);
}

// ---------------------------------------------------------------------------
// Kernel 1: LSTM recurrence. 32 blocks = (2 dirs) x (16 batch lanes).
// ---------------------------------------------------------------------------
__global__ void lstm_kernel(const float* __restrict__ W_hh,
                            const float* __restrict__ init_h,
                            const float* __restrict__ init_c) {
    int dir = blockIdx.x >> 4;
    int b   = blockIdx.x & 15;
    int j   = threadIdx.x;

    __shared__ float h_sh[kHID];
    __shared__ float gact[kG];

    float w[kHID];
#pragma unroll
    for (int k = 0; k < kHID; ++k) w[k] = W_hh[j * kHID + k];

    float c_reg = 0.f, h_reg = 0.f;
    if (j < kHID) {
        h_reg = init_h[j];
        c_reg = init_c[j];
        h_sh[j] = h_reg;
    }
    __syncthreads();

    int p  = dir ? (kS - 1) : 0;
    int dp = dir ? -1 : 1;
    float gx_next = g_gx[(p * kB + b) * kG + j];

    for (int step = 0; step < kS; ++step, p += dp) {
        float gxv = gx_next;
        if (step < kS - 1) gx_next = g_gx[((p + dp) * kB + b) * kG + j];

        if (j < kHID)
            g_concat[(p * kB + b) * (2 * kHID) + dir * kHID + j] = h_reg;

        float a0 = 0.f, a1 = 0.f, a2 = 0.f, a3 = 0.f;
#pragma unroll
        for (int k = 0; k < kHID; k += 4) {
            a0 += w[k + 0] * h_sh[k + 0];
            a1 += w[k + 1] * h_sh[k + 1];
            a2 += w[k + 2] * h_sh[k + 2];
            a3 += w[k + 3] * h_sh[k + 3];
        }
        float pre = gxv + ((a0 + a1) + (a2 + a3));
        gact[j] = (j >= 32 && j < 48) ? tanhfast(pre) : sigf(pre);
        __syncthreads();

        if (j < kHID) {
            float ig = gact[j];
            float fg = gact[kHID + j];
            float gg = gact[2 * kHID + j];
            float og = gact[3 * kHID + j];
            c_reg = fg * c_reg + ig * gg;
            h_reg = og * tanhfast(c_reg);
            h_sh[j] = h_reg;
        }
        __syncthreads();
    }
}

// ---------------------------------------------------------------------------
// Prep kernels: convert W_out / g_concat to bf16 fragment-order in gmem.
// Tiles become contiguous 12KB blocks -> pure cp.async staging in mma_pass.
// ---------------------------------------------------------------------------
__global__ void prepb_kernel(const float* __restrict__ W_out) {
    int i = blockIdx.x * 256 + threadIdx.x;       // over kV*8 float4s
    float4 v = reinterpret_cast<const float4*>(W_out)[i];
    int r = i >> 3, j = i & 7;
    uint32_t* dst = g_bbf + r * kFS;
    dst[fragcol(2 * j)]     = pack_bf16(v.x, v.y);
    dst[fragcol(2 * j + 1)] = pack_bf16(v.z, v.w);
}

__global__ void prepa_kernel() {
    int i = blockIdx.x * 256 + threadIdx.x;       // over kRows*8 float4s
    float4 v = reinterpret_cast<const float4*>(g_concat)[i];
    int r = i >> 3, j = i & 7;
    int c0 = fragcol(2 * j), c1 = fragcol(2 * j + 1);
    g_abf2[r * kFS + c0] = pack_bf16(v.x, v.y);
    g_abf2[r * kFS + c1] = pack_bf16(v.z, v.w);
    g_abf1[r * kFS + c0] = pack_bf16(v.x * kLOG2E, v.y * kLOG2E);
    g_abf1[r * kFS + c1] = pack_bf16(v.z * kLOG2E, v.w * kLOG2E);
}

// ---------------------------------------------------------------------------
// Kernel 2: bf16 tensor-core logits GEMM. Grid (250, 8). Each CTA cp.asyncs
// its B tile + ALL 4 A tiles up front (5 commit groups, 60KB smem), then the
// m-loop is wait_group/barrier/MMA only — no mid-loop global latency, no
// conversion ALU. Pass 1: Σ ex2 -> g_part. Pass 2: acc init = b - logZ ->
// direct fragment streaming stores.
// ---------------------------------------------------------------------------
template <bool WRITE>
__global__ void __launch_bounds__(256, 2)
mma_pass(const float* __restrict__ b_out, float* __restrict__ out) {
    extern __shared__ uint32_t dynsm[];
    uint32_t* A_sm   = dynsm;                       // [4][3072]
    uint32_t* B_sm   = dynsm + 4 * kTileU32;        // [3072]
    float*    bias_sm = reinterpret_cast<float*>(dynsm + 5 * kTileU32);  // [128]
    float*    lz_sm   = bias_sm + kNT;              // [512]

    int tid  = threadIdx.x;
    int warp = tid >> 5;
    int lane = tid & 31;
    int tg   = lane & 3;
    int gr   = lane >> 2;
    int n0   = blockIdx.x * kNT;
    int mrow = warp * 16;
    int rbase = blockIdx.y * kMLoop * kMT;          // 512 rows per CTA

    // B tile: contiguous 12KB from g_bbf
    {
        uint32_t bdst = (uint32_t)__cvta_generic_to_shared(B_sm);
        const uint4* src = reinterpret_cast<const uint4*>(
            g_bbf + (size_t)n0 * kFS);
        for (int i = tid; i < kTileU32 / 4; i += 256)
            cp16(bdst + i * 16, src + i);
        CP_COMMIT();
    }
    // A tiles: 4 contiguous 12KB blocks
    const uint32_t* asrc_base = WRITE ? g_abf2 : g_abf1;
#pragma unroll
    for (int mi = 0; mi < kMLoop; ++mi) {
        uint32_t adst = (uint32_t)__cvta_generic_to_shared(A_sm + mi * kTileU32);
        const uint4* src = reinterpret_cast<const uint4*>(
            asrc_base + (size_t)(rbase + mi * kMT) * kFS);
        for (int i = tid; i < kTileU32 / 4; i += 256)
            cp16(adst + i * 16, src + i);
        CP_COMMIT();
    }
    // bias + lz (regular loads; published by first barrier)
    if (tid < kNT) bias_sm[tid] = WRITE ? b_out[n0 + tid]
                                        : b_out[n0 + tid] * kLOG2E;
    if (WRITE) {
        for (int i = tid; i < kMLoop * kMT; i += 256)
            lz_sm[i] = g_lz[rbase + i];
    }

#pragma unroll
    for (int mi = 0; mi < kMLoop; ++mi) {
        switch (mi) {   // wait until B + A[0..mi] groups complete
            case 0:  CP_WAIT(3); break;
            case 1:  CP_WAIT(2); break;
            case 2:  CP_WAIT(1); break;
            default: CP_WAIT(0); break;
        }
        __syncthreads();

        int row0 = rbase + mi * kMT;
        const uint32_t* At = A_sm + mi * kTileU32;

        float c[16][4];
#pragma unroll
        for (int f = 0; f < 16; ++f) {
            float bx = bias_sm[f * 8 + tg * 2];
            float by = bias_sm[f * 8 + tg * 2 + 1];
            if (WRITE) {
                float z0 = lz_sm[mi * kMT + mrow + gr];
                float z1 = lz_sm[mi * kMT + mrow + gr + 8];
                c[f][0] = bx - z0; c[f][1] = by - z0;
                c[f][2] = bx - z1; c[f][3] = by - z1;
            } else {
                c[f][0] = bx; c[f][1] = by;
                c[f][2] = bx; c[f][3] = by;
            }
        }

        const uint32_t* ar0 = At + (mrow + gr) * kFS + tg * 2;
        const uint32_t* ar1 = At + (mrow + gr + 8) * kFS + tg * 2;
        uint2 alo0 = *reinterpret_cast<const uint2*>(ar0);
        uint2 alo1 = *reinterpret_cast<const uint2*>(ar1);
        uint2 ahi0 = *reinterpret_cast<const uint2*>(ar0 + 8);
        uint2 ahi1 = *reinterpret_cast<const uint2*>(ar1 + 8);
        const uint32_t* bp = B_sm + gr * kFS + tg * 2;

#pragma unroll
        for (int f = 0; f < 16; ++f) {
            uint2 blo = *reinterpret_cast<const uint2*>(bp + f * 8 * kFS);
            uint2 bhi = *reinterpret_cast<const uint2*>(bp + f * 8 * kFS + 8);
            mma_bf16(c[f], alo0.x, alo1.x, alo0.y, alo1.y, blo.x, blo.y);
            mma_bf16(c[f], ahi0.x, ahi1.x, ahi0.y, ahi1.y, bhi.x, bhi.y);
        }

        if (!WRITE) {
            float s0 = 0.f, s1 = 0.f;
#pragma unroll
            for (int f = 0; f < 16; ++f) {
                s0 += ex2f(c[f][0]) + ex2f(c[f][1]);
                s1 += ex2f(c[f][2]) + ex2f(c[f][3]);
            }
            s0 += __shfl_xor_sync(0xffffffffu, s0, 1);
            s0 += __shfl_xor_sync(0xffffffffu, s0, 2);
            s1 += __shfl_xor_sync(0xffffffffu, s1, 1);
            s1 += __shfl_xor_sync(0xffffffffu, s1, 2);
            if (tg == 0) {
                g_part[(size_t)blockIdx.x * kRows + row0 + mrow + gr]     = s0;
                g_part[(size_t)blockIdx.x * kRows + row0 + mrow + gr + 8] = s1;
            }
        } else {
            float* orow0 = out + (size_t)(row0 + mrow + gr) * kV + n0 + tg * 2;
            float* orow1 = orow0 + (size_t)8 * kV;
#pragma unroll
            for (int f = 0; f < 16; ++f) {
                __stcs(reinterpret_cast<float2*>(orow0 + f * 8),
                       make_float2(c[f][0], c[f][1]));
                __stcs(reinterpret_cast<float2*>(orow1 + f * 8),
                       make_float2(c[f][2], c[f][3]));
            }
        }
    }
}

// ---------------------------------------------------------------------------
// Kernel 3: logZ reduce. 128 blocks x 256 threads = 32 rows x 8 t-slices.
// ---------------------------------------------------------------------------
__global__ void logz_kernel() {
    __shared__ float red[8][32];
    int rl    = threadIdx.x & 31;
    int slice = threadIdx.x >> 5;
    int row   = blockIdx.x * 32 + rl;

    float s = 0.f;
#pragma unroll 4
    for (int t = slice; t < kNTiles; t += 8)
        s += g_part[(size_t)t * kRows + row];
    red[slice][rl] = s;
    __syncthreads();

    if (slice == 0) {
        float tot = 0.f;
#pragma unroll
        for (int i = 0; i < 8; ++i) tot += red[i][rl];
        g_lz[row] = __logf(tot);
    }
}

// ---------------------------------------------------------------------------
extern "C" void kernel_launch(void* const* d_in, const int* in_sizes, int n_in,
                              void* d_out, int out_size) {
    const int*   tokens = (const int*)d_in[0];
    const float* emb    = (const float*)d_in[1];
    const float* W_ih   = (const float*)d_in[2];
    const float* W_hh   = (const float*)d_in[3];
    const float* b_ih   = (const float*)d_in[4];
    const float* b_hh   = (const float*)d_in[5];
    const float* W_out  = (const float*)d_in[6];
    const float* b_out  = (const float*)d_in[7];
    const float* init_h = (const float*)d_in[8];
    const float* init_c = (const float*)d_in[9];
    float* out = (float*)d_out;

    static bool attr_set = false;
    if (!attr_set) {
        cudaFuncSetAttribute(mma_pass<false>,
                             cudaFuncAttributeMaxDynamicSharedMemorySize,
                             kSmemBytes);
        cudaFuncSetAttribute(mma_pass<true>,
                             cudaFuncAttributeMaxDynamicSharedMemorySize,
                             kSmemBytes);
        attr_set = true;
    }

    dim3 grid(kNTiles, kYBlk);

    prepb_kernel<<<kV * 8 / 256, 256>>>(W_out);
    gx_kernel<<<(kS * kB) / 4, 256>>>(tokens, emb, W_ih, b_ih, b_hh);
    lstm_kernel<<<32, 64>>>(W_hh, init_h, init_c);
    prepa_kernel<<<kRows * 8 / 256, 256>>>();
    mma_pass<false><<<grid, 256, kSmemBytes>>>(b_out, out);
    logz_kernel<<<kRows / 32, 256>>>();
    mma_pass<true><<<grid, 256, kSmemBytes>>>(b_out, out);
}

// round 12
// speedup vs baseline: 1.2563x; 1.0909x over previous
#include <cuda_runtime.h>
#include <cuda_bf16.h>
#include <cstdint>

// Problem constants
static constexpr int kS    = 256;
static constexpr int kB    = 16;
static constexpr int kV    = 32000;
static constexpr int kEMB  = 32;
static constexpr int kHID  = 16;
static constexpr int kG    = 4 * kHID;     // 64 gates
static constexpr int kRows = kS * kB;      // 4096
static constexpr int kMT   = 128;          // rows per m tile
static constexpr int kNT   = 128;          // cols per CTA (n tile)
static constexpr int kNTiles = kV / kNT;   // 250
static constexpr int kMTiles = kRows / kMT; // 32
static constexpr int kMLoop = 4;           // m tiles per CTA
static constexpr int kYBlk  = kMTiles / kMLoop;  // 8
static constexpr int kFS   = 24;           // u32 row stride (conflict-free LDS)
static constexpr int kTileU32 = kMT * kFS; // 3072 u32 = 12KB per tile

static constexpr float kLOG2E = 1.4426950408889634f;

// dynamic smem: A[4] tiles + B tile + bias + lz
static constexpr int kSmemBytes =
    (4 * kTileU32 + kTileU32) * 4 + kNT * 4 + kMLoop * kMT * 4;  // 64 KB

// Scratch (static __device__ — no allocations allowed)
__device__ float    g_gx[kS * kB * kG];
__device__ float    g_concat[kRows * 2 * kHID];   // A matrix [4096][32] f32
__device__ uint32_t g_abf1[kRows * kFS];          // A bf16-frag, x log2(e)
__device__ uint32_t g_abf2[kRows * kFS];          // A bf16-frag, plain
__device__ uint32_t g_bbf[kV * kFS];              // W_out bf16-frag, col-permuted
__device__ float    g_part[kNTiles * kRows];      // per-(ntile,row) exp-sums
__device__ float    g_lz[kRows];                  // per-row logZ

__device__ __forceinline__ float sigf(float x) {
    return 1.0f / (1.0f + __expf(-x));
}
__device__ __forceinline__ float tanhfast(float x) {
    return 2.0f / (1.0f + __expf(-2.0f * x)) - 1.0f;
}
__device__ __forceinline__ float ex2f(float x) {
    float y;
    asm("ex2.approx.ftz.f32 %0, %1;" : "=f"(y) : "f"(x));
    return y;
}
__device__ __forceinline__ uint32_t pack_bf16(float lo, float hi) {
    __nv_bfloat162 h = __floats2bfloat162_rn(lo, hi);
    return *reinterpret_cast<uint32_t*>(&h);
}
__device__ __forceinline__ void mma_bf16(float c[4], uint32_t a0, uint32_t a1,
                                         uint32_t a2, uint32_t a3,
                                         uint32_t b0, uint32_t b1) {
    asm("mma.sync.aligned.m16n8k16.row.col.f32.bf16.bf16.f32 "
        "{%0,%1,%2,%3}, {%4,%5,%6,%7}, {%8,%9}, {%0,%1,%2,%3};"
        : "+f"(c[0]), "+f"(c[1]), "+f"(c[2]), "+f"(c[3])
        : "r"(a0), "r"(a1), "r"(a2), "r"(a3), "r"(b0), "r"(b1));
}
__device__ __forceinline__ void cp16(uint32_t sdst, const void* gsrc) {
    asm volatile("cp.async.cg.shared.global [%0], [%1], 16;"
                 :: "r"(sdst), "l"(gsrc));
}
#define CP_COMMIT() asm volatile("cp.async.commit_group;")
#define CP_WAIT(N)  asm volatile("cp.async.wait_group %0;" :: "n"(N))

// fragment column for k-pair p (p = k/2, 0..15)
__device__ __forceinline__ int fragcol(int p) {
    return 2 * (p & 3) + ((p >> 2) & 1) + (p >> 3) * 8;
}
// Column permutation within a 128-col tile: logical col l sits at physical
// mma position (frag, slot) such that thread tg's fragment-pair slots hold
// 4 CONSECUTIVE logical columns (enables STG.128 in pass 2):
//   l = 16q + 4tg + e  ->  frag = 2q + (e>>1), pos_in_frag = tg*2 + (e&1)
__device__ __forceinline__ int permrow(int l) {
    int q = l >> 4, tgp = (l >> 2) & 3, e = l & 3;
    return (2 * q + (e >> 1)) * 8 + tgp * 2 + (e & 1);
}

// ---------------------------------------------------------------------------
// Kernel 0: Gx = x@W_ih.T + b_ih + b_hh (shared by both scan directions)
// ---------------------------------------------------------------------------
__global__ void gx_kernel(const int* __restrict__ tokens,
                          const float* __restrict__ emb,
                          const float* __restrict__ W_ih,
                          const float* __restrict__ b_ih,
                          const float* __restrict__ b_hh) {
    __shared__ float ws[kG * 33];
    __shared__ float xs[4][32];
    __shared__ float bb[kG];

    int tid = threadIdx.x;
    for (int i = tid; i < kG * kEMB; i += 256)
        ws[(i >> 5) * 33 + (i & 31)] = W_ih[i];
    if (tid < kG) bb[tid] = b_ih[tid] + b_hh[tid];

    int sb0 = blockIdx.x * 4;
    if (tid < 128) {
        int g = tid >> 5, k = tid & 31;
        xs[g][k] = emb[(size_t)tokens[sb0 + g] * kEMB + k];
    }
    __syncthreads();

    int g = tid >> 6;
    int j = tid & (kG - 1);
    const float* wr = ws + j * 33;
    float a0 = bb[j], a1 = 0.f, a2 = 0.f, a3 = 0.f;
#pragma unroll
    for (int k = 0; k < kEMB; k += 4) {
        a0 += xs[g][k + 0] * wr[k + 0];
        a1 += xs[g][k + 1] * wr[k + 1];
        a2 += xs[g][k + 2] * wr[k + 2];
        a3 += xs[g][k + 3] * wr[k + 3];
    }
    g_gx[(sb0 + g) * kG + j] = (a0 + a1) + (a2 + a3);
}

// ---------------------------------------------------------------------------
// Kernel 1: LSTM recurrence. 32 blocks = (2 dirs) x (16 batch lanes).
// ---------------------------------------------------------------------------
__global__ void lstm_kernel(const float* __restrict__ W_hh,
                            const float* __restrict__ init_h,
                            const float* __restrict__ init_c) {
    int dir = blockIdx.x >> 4;
    int b   = blockIdx.x & 15;
    int j   = threadIdx.x;

    __shared__ float h_sh[kHID];
    __shared__ float gact[kG];

    float w[kHID];
#pragma unroll
    for (int k = 0; k < kHID; ++k) w[k] = W_hh[j * kHID + k];

    float c_reg = 0.f, h_reg = 0.f;
    if (j < kHID) {
        h_reg = init_h[j];
        c_reg = init_c[j];
        h_sh[j] = h_reg;
    }
    __syncthreads();

    int p  = dir ? (kS - 1) : 0;
    int dp = dir ? -1 : 1;
    float gx_next = g_gx[(p * kB + b) * kG + j];

    for (int step = 0; step < kS; ++step, p += dp) {
        float gxv = gx_next;
        if (step < kS - 1) gx_next = g_gx[((p + dp) * kB + b) * kG + j];

        if (j < kHID)
            g_concat[(p * kB + b) * (2 * kHID) + dir * kHID + j] = h_reg;

        float a0 = 0.f, a1 = 0.f, a2 = 0.f, a3 = 0.f;
#pragma unroll
        for (int k = 0; k < kHID; k += 4) {
            a0 += w[k + 0] * h_sh[k + 0];
            a1 += w[k + 1] * h_sh[k + 1];
            a2 += w[k + 2] * h_sh[k + 2];
            a3 += w[k + 3] * h_sh[k + 3];
        }
        float pre = gxv + ((a0 + a1) + (a2 + a3));
        gact[j] = (j >= 32 && j < 48) ? tanhfast(pre) : sigf(pre);
        __syncthreads();

        if (j < kHID) {
            float ig = gact[j];
            float fg = gact[kHID + j];
            float gg = gact[2 * kHID + j];
            float og = gact[3 * kHID + j];
            c_reg = fg * c_reg + ig * gg;
            h_reg = og * tanhfast(c_reg);
            h_sh[j] = h_reg;
        }
        __syncthreads();
    }
}

// ---------------------------------------------------------------------------
// Prep kernels. prepb applies the within-tile column permutation (permrow)
// so pass-2 threads own 4 consecutive logical columns.
// ---------------------------------------------------------------------------
__global__ void prepb_kernel(const float* __restrict__ W_out) {
    int i = blockIdx.x * 256 + threadIdx.x;       // over kV*8 float4s
    float4 v = reinterpret_cast<const float4*>(W_out)[i];
    int n = i >> 3, j = i & 7;
    int rp = (n & ~127) + permrow(n & 127);       // permuted physical row
    uint32_t* dst = g_bbf + (size_t)rp * kFS;
    dst[fragcol(2 * j)]     = pack_bf16(v.x, v.y);
    dst[fragcol(2 * j + 1)] = pack_bf16(v.z, v.w);
}

__global__ void prepa_kernel() {
    int i = blockIdx.x * 256 + threadIdx.x;       // over kRows*8 float4s
    float4 v = reinterpret_cast<const float4*>(g_concat)[i];
    int r = i >> 3, j = i & 7;
    int c0 = fragcol(2 * j), c1 = fragcol(2 * j + 1);
    g_abf2[r * kFS + c0] = pack_bf16(v.x, v.y);
    g_abf2[r * kFS + c1] = pack_bf16(v.z, v.w);
    g_abf1[r * kFS + c0] = pack_bf16(v.x * kLOG2E, v.y * kLOG2E);
    g_abf1[r * kFS + c1] = pack_bf16(v.z * kLOG2E, v.w * kLOG2E);
}

// ---------------------------------------------------------------------------
// Kernel 2: bf16 tensor-core logits GEMM. Grid (250, 8). cp.async prefetch of
// B + 4 A tiles at CTA start; m-loop is wait/barrier/MMA only.
// Pass 1: Σ ex2 -> g_part (column-permutation invariant).
// Pass 2: acc init = b - logZ -> STG.128 of 4 consecutive logical columns.
// ---------------------------------------------------------------------------
template <bool WRITE>
__global__ void __launch_bounds__(256, 2)
mma_pass(const float* __restrict__ b_out, float* __restrict__ out) {
    extern __shared__ uint32_t dynsm[];
    uint32_t* A_sm   = dynsm;                       // [4][3072]
    uint32_t* B_sm   = dynsm + 4 * kTileU32;        // [3072]
    float*    bias_sm = reinterpret_cast<float*>(dynsm + 5 * kTileU32);  // [128]
    float*    lz_sm   = bias_sm + kNT;              // [512]

    int tid  = threadIdx.x;
    int warp = tid >> 5;
    int lane = tid & 31;
    int tg   = lane & 3;
    int gr   = lane >> 2;
    int n0   = blockIdx.x * kNT;
    int mrow = warp * 16;
    int rbase = blockIdx.y * kMLoop * kMT;          // 512 rows per CTA

    // B tile: contiguous 12KB from g_bbf
    {
        uint32_t bdst = (uint32_t)__cvta_generic_to_shared(B_sm);
        const uint4* src = reinterpret_cast<const uint4*>(
            g_bbf + (size_t)n0 * kFS);
        for (int i = tid; i < kTileU32 / 4; i += 256)
            cp16(bdst + i * 16, src + i);
        CP_COMMIT();
    }
    // A tiles: 4 contiguous 12KB blocks
    const uint32_t* asrc_base = WRITE ? g_abf2 : g_abf1;
#pragma unroll
    for (int mi = 0; mi < kMLoop; ++mi) {
        uint32_t adst = (uint32_t)__cvta_generic_to_shared(A_sm + mi * kTileU32);
        const uint4* src = reinterpret_cast<const uint4*>(
            asrc_base + (size_t)(rbase + mi * kMT) * kFS);
        for (int i = tid; i < kTileU32 / 4; i += 256)
            cp16(adst + i * 16, src + i);
        CP_COMMIT();
    }
    // bias (stored in PHYSICAL fragment order, matching permuted B) + lz
    if (tid < kNT) {
        int frag = tid >> 3, pos = tid & 7;
        int l = 16 * (frag >> 1) + 4 * (pos >> 1) + 2 * (frag & 1) + (pos & 1);
        float bv = b_out[n0 + l];
        bias_sm[tid] = WRITE ? bv : bv * kLOG2E;
    }
    if (WRITE) {
        for (int i = tid; i < kMLoop * kMT; i += 256)
            lz_sm[i] = g_lz[rbase + i];
    }

#pragma unroll
    for (int mi = 0; mi < kMLoop; ++mi) {
        switch (mi) {   // wait until B + A[0..mi] groups complete
            case 0:  CP_WAIT(3); break;
            case 1:  CP_WAIT(2); break;
            case 2:  CP_WAIT(1); break;
            default: CP_WAIT(0); break;
        }
        __syncthreads();

        int row0 = rbase + mi * kMT;
        const uint32_t* At = A_sm + mi * kTileU32;

        float c[16][4];
#pragma unroll
        for (int f = 0; f < 16; ++f) {
            float bx = bias_sm[f * 8 + tg * 2];
            float by = bias_sm[f * 8 + tg * 2 + 1];
            if (WRITE) {
                float z0 = lz_sm[mi * kMT + mrow + gr];
                float z1 = lz_sm[mi * kMT + mrow + gr + 8];
                c[f][0] = bx - z0; c[f][1] = by - z0;
                c[f][2] = bx - z1; c[f][3] = by - z1;
            } else {
                c[f][0] = bx; c[f][1] = by;
                c[f][2] = bx; c[f][3] = by;
            }
        }

        const uint32_t* ar0 = At + (mrow + gr) * kFS + tg * 2;
        const uint32_t* ar1 = At + (mrow + gr + 8) * kFS + tg * 2;
        uint2 alo0 = *reinterpret_cast<const uint2*>(ar0);
        uint2 alo1 = *reinterpret_cast<const uint2*>(ar1);
        uint2 ahi0 = *reinterpret_cast<const uint2*>(ar0 + 8);
        uint2 ahi1 = *reinterpret_cast<const uint2*>(ar1 + 8);
        const uint32_t* bp = B_sm + gr * kFS + tg * 2;

#pragma unroll
        for (int f = 0; f < 16; ++f) {
            uint2 blo = *reinterpret_cast<const uint2*>(bp + f * 8 * kFS);
            uint2 bhi = *reinterpret_cast<const uint2*>(bp + f * 8 * kFS + 8);
            mma_bf16(c[f], alo0.x, alo1.x, alo0.y, alo1.y, blo.x, blo.y);
            mma_bf16(c[f], ahi0.x, ahi1.x, ahi0.y, ahi1.y, bhi.x, bhi.y);
        }

        if (!WRITE) {
            float s0 = 0.f, s1 = 0.f;
#pragma unroll
            for (int f = 0; f < 16; ++f) {
                s0 += ex2f(c[f][0]) + ex2f(c[f][1]);
                s1 += ex2f(c[f][2]) + ex2f(c[f][3]);
            }
            s0 += __shfl_xor_sync(0xffffffffu, s0, 1);
            s0 += __shfl_xor_sync(0xffffffffu, s0, 2);
            s1 += __shfl_xor_sync(0xffffffffu, s1, 1);
            s1 += __shfl_xor_sync(0xffffffffu, s1, 2);
            if (tg == 0) {
                g_part[(size_t)blockIdx.x * kRows + row0 + mrow + gr]     = s0;
                g_part[(size_t)blockIdx.x * kRows + row0 + mrow + gr + 8] = s1;
            }
        } else {
            // STG.128: frag pair (2q,2q+1) slots = logical cols 16q+4tg..+3
            float* orow0 = out + (size_t)(row0 + mrow + gr) * kV + n0 + tg * 4;
            float* orow1 = orow0 + (size_t)8 * kV;
#pragma unroll
            for (int q = 0; q < 8; ++q) {
                __stcs(reinterpret_cast<float4*>(orow0 + q * 16),
                       make_float4(c[2 * q][0], c[2 * q][1],
                                   c[2 * q + 1][0], c[2 * q + 1][1]));
                __stcs(reinterpret_cast<float4*>(orow1 + q * 16),
                       make_float4(c[2 * q][2], c[2 * q][3],
                                   c[2 * q + 1][2], c[2 * q + 1][3]));
            }
        }
    }
}

// ---------------------------------------------------------------------------
// Kernel 3: logZ reduce. 128 blocks x 256 threads = 32 rows x 8 t-slices.
// ---------------------------------------------------------------------------
__global__ void logz_kernel() {
    __shared__ float red[8][32];
    int rl    = threadIdx.x & 31;
    int slice = threadIdx.x >> 5;
    int row   = blockIdx.x * 32 + rl;

    float s = 0.f;
#pragma unroll 4
    for (int t = slice; t < kNTiles; t += 8)
        s += g_part[(size_t)t * kRows + row];
    red[slice][rl] = s;
    __syncthreads();

    if (slice == 0) {
        float tot = 0.f;
#pragma unroll
        for (int i = 0; i < 8; ++i) tot += red[i][rl];
        g_lz[row] = __logf(tot);
    }
}

// ---------------------------------------------------------------------------
extern "C" void kernel_launch(void* const* d_in, const int* in_sizes, int n_in,
                              void* d_out, int out_size) {
    const int*   tokens = (const int*)d_in[0];
    const float* emb    = (const float*)d_in[1];
    const float* W_ih   = (const float*)d_in[2];
    const float* W_hh   = (const float*)d_in[3];
    const float* b_ih   = (const float*)d_in[4];
    const float* b_hh   = (const float*)d_in[5];
    const float* W_out  = (const float*)d_in[6];
    const float* b_out  = (const float*)d_in[7];
    const float* init_h = (const float*)d_in[8];
    const float* init_c = (const float*)d_in[9];
    float* out = (float*)d_out;

    static cudaStream_t s1 = nullptr;
    static cudaEvent_t evFork = nullptr, evB = nullptr;
    static bool attr_set = false;
    if (!attr_set) {
        cudaFuncSetAttribute(mma_pass<false>,
                             cudaFuncAttributeMaxDynamicSharedMemorySize,
                             kSmemBytes);
        cudaFuncSetAttribute(mma_pass<true>,
                             cudaFuncAttributeMaxDynamicSharedMemorySize,
                             kSmemBytes);
        cudaStreamCreateWithFlags(&s1, cudaStreamNonBlocking);
        cudaEventCreateWithFlags(&evFork, cudaEventDisableTiming);
        cudaEventCreateWithFlags(&evB, cudaEventDisableTiming);
        attr_set = true;
    }

    dim3 grid(kNTiles, kYBlk);

    // fork: prepb (depends only on W_out) overlaps gx+lstm+prepa
    cudaEventRecord(evFork, 0);
    cudaStreamWaitEvent(s1, evFork, 0);
    prepb_kernel<<<kV * 8 / 256, 256, 0, s1>>>(W_out);
    cudaEventRecord(evB, s1);

    gx_kernel<<<(kS * kB) / 4, 256>>>(tokens, emb, W_ih, b_ih, b_hh);
    lstm_kernel<<<32, 64>>>(W_hh, init_h, init_c);
    prepa_kernel<<<kRows * 8 / 256, 256>>>();
    cudaStreamWaitEvent(0, evB, 0);

    mma_pass<false><<<grid, 256, kSmemBytes>>>(b_out, out);
    logz_kernel<<<kRows / 32, 256>>>();
    mma_pass<true><<<grid, 256, kSmemBytes>>>(b_out, out);
}

// round 13
// speedup vs baseline: 1.2738x; 1.0140x over previous
#include <cuda_runtime.h>
#include <cuda_bf16.h>
#include <cstdint>

// Problem constants
static constexpr int kS    = 256;
static constexpr int kB    = 16;
static constexpr int kV    = 32000;
static constexpr int kEMB  = 32;
static constexpr int kHID  = 16;
static constexpr int kG    = 4 * kHID;     // 64 gates
static constexpr int kRows = kS * kB;      // 4096
static constexpr int kMT   = 128;          // rows per m tile
static constexpr int kNT   = 128;          // cols per CTA (n tile)
static constexpr int kNTiles = kV / kNT;   // 250
static constexpr int kMTiles = kRows / kMT; // 32
static constexpr int kMLoop = 4;           // m tiles per CTA
static constexpr int kYBlk  = kMTiles / kMLoop;  // 8
static constexpr int kFS   = 24;           // u32 row stride (conflict-free LDS)
static constexpr int kTileU32 = kMT * kFS; // 3072 u32 = 12KB per tile

static constexpr float kLOG2E = 1.4426950408889634f;

// dynamic smem: A[4] tiles + B tile + bias + lz
static constexpr int kSmemBytes =
    (4 * kTileU32 + kTileU32) * 4 + kNT * 4 + kMLoop * kMT * 4;  // 64 KB

// Scratch (static __device__ — no allocations allowed)
__device__ float    g_gx[kS * kB * kG];
__device__ float    g_concat[kRows * 2 * kHID];   // A matrix [4096][32] f32
__device__ uint32_t g_abf1[kRows * kFS];          // A bf16-frag, x log2(e)
__device__ uint32_t g_abf2[kRows * kFS];          // A bf16-frag, plain
__device__ uint32_t g_bbf[kV * kFS];              // W_out bf16-frag, col-permuted
__device__ float    g_part[kNTiles * kRows];      // per-(ntile,row) exp-sums
__device__ float    g_lz[kRows];                  // per-row logZ

__device__ __forceinline__ float sigf(float x) {
    return 1.0f / (1.0f + __expf(-x));
}
__device__ __forceinline__ float tanhfast(float x) {
    return 2.0f / (1.0f + __expf(-2.0f * x)) - 1.0f;
}
__device__ __forceinline__ float ex2f(float x) {
    float y;
    asm("ex2.approx.ftz.f32 %0, %1;" : "=f"(y) : "f"(x));
    return y;
}
__device__ __forceinline__ uint32_t pack_bf16(float lo, float hi) {
    __nv_bfloat162 h = __floats2bfloat162_rn(lo, hi);
    return *reinterpret_cast<uint32_t*>(&h);
}
__device__ __forceinline__ void mma_bf16(float c[4], uint32_t a0, uint32_t a1,
                                         uint32_t a2, uint32_t a3,
                                         uint32_t b0, uint32_t b1) {
    asm("mma.sync.aligned.m16n8k16.row.col.f32.bf16.bf16.f32 "
        "{%0,%1,%2,%3}, {%4,%5,%6,%7}, {%8,%9}, {%0,%1,%2,%3};"
        : "+f"(c[0]), "+f"(c[1]), "+f"(c[2]), "+f"(c[3])
        : "r"(a0), "r"(a1), "r"(a2), "r"(a3), "r"(b0), "r"(b1));
}
__device__ __forceinline__ void cp16(uint32_t sdst, const void* gsrc) {
    asm volatile("cp.async.cg.shared.global [%0], [%1], 16;"
                 :: "r"(sdst), "l"(gsrc));
}
#define CP_COMMIT() asm volatile("cp.async.commit_group;")
#define CP_WAIT(N)  asm volatile("cp.async.wait_group %0;" :: "n"(N))

// fragment column for k-pair p (p = k/2, 0..15)
__device__ __forceinline__ int fragcol(int p) {
    return 2 * (p & 3) + ((p >> 2) & 1) + (p >> 3) * 8;
}
// Column permutation within a 128-col tile (pass-2 STG.128 enabling):
//   l = 16q + 4tg + e  ->  frag = 2q + (e>>1), pos_in_frag = tg*2 + (e&1)
__device__ __forceinline__ int permrow(int l) {
    int q = l >> 4, tgp = (l >> 2) & 3, e = l & 3;
    return (2 * q + (e >> 1)) * 8 + tgp * 2 + (e & 1);
}

// ---------------------------------------------------------------------------
// Kernel 0: Gx = x@W_ih.T + b_ih + b_hh (shared by both scan directions)
// ---------------------------------------------------------------------------
__global__ void gx_kernel(const int* __restrict__ tokens,
                          const float* __restrict__ emb,
                          const float* __restrict__ W_ih,
                          const float* __restrict__ b_ih,
                          const float* __restrict__ b_hh) {
    __shared__ float ws[kG * 33];
    __shared__ float xs[4][32];
    __shared__ float bb[kG];

    int tid = threadIdx.x;
    for (int i = tid; i < kG * kEMB; i += 256)
        ws[(i >> 5) * 33 + (i & 31)] = W_ih[i];
    if (tid < kG) bb[tid] = b_ih[tid] + b_hh[tid];

    int sb0 = blockIdx.x * 4;
    if (tid < 128) {
        int g = tid >> 5, k = tid & 31;
        xs[g][k] = emb[(size_t)tokens[sb0 + g] * kEMB + k];
    }
    __syncthreads();

    int g = tid >> 6;
    int j = tid & (kG - 1);
    const float* wr = ws + j * 33;
    float a0 = bb[j], a1 = 0.f, a2 = 0.f, a3 = 0.f;
#pragma unroll
    for (int k = 0; k < kEMB; k += 4) {
        a0 += xs[g][k + 0] * wr[k + 0];
        a1 += xs[g][k + 1] * wr[k + 1];
        a2 += xs[g][k + 2] * wr[k + 2];
        a3 += xs[g][k + 3] * wr[k + 3];
    }
    g_gx[(sb0 + g) * kG + j] = (a0 + a1) + (a2 + a3);
}

// ---------------------------------------------------------------------------
// Kernel 1: LSTM recurrence. 32 blocks = (2 dirs) x (16 batch lanes).
// ---------------------------------------------------------------------------
__global__ void lstm_kernel(const float* __restrict__ W_hh,
                            const float* __restrict__ init_h,
                            const float* __restrict__ init_c) {
    int dir = blockIdx.x >> 4;
    int b   = blockIdx.x & 15;
    int j   = threadIdx.x;

    __shared__ float h_sh[kHID];
    __shared__ float gact[kG];

    float w[kHID];
#pragma unroll
    for (int k = 0; k < kHID; ++k) w[k] = W_hh[j * kHID + k];

    float c_reg = 0.f, h_reg = 0.f;
    if (j < kHID) {
        h_reg = init_h[j];
        c_reg = init_c[j];
        h_sh[j] = h_reg;
    }
    __syncthreads();

    int p  = dir ? (kS - 1) : 0;
    int dp = dir ? -1 : 1;
    float gx_next = g_gx[(p * kB + b) * kG + j];

    for (int step = 0; step < kS; ++step, p += dp) {
        float gxv = gx_next;
        if (step < kS - 1) gx_next = g_gx[((p + dp) * kB + b) * kG + j];

        if (j < kHID)
            g_concat[(p * kB + b) * (2 * kHID) + dir * kHID + j] = h_reg;

        float a0 = 0.f, a1 = 0.f, a2 = 0.f, a3 = 0.f;
#pragma unroll
        for (int k = 0; k < kHID; k += 4) {
            a0 += w[k + 0] * h_sh[k + 0];
            a1 += w[k + 1] * h_sh[k + 1];
            a2 += w[k + 2] * h_sh[k + 2];
            a3 += w[k + 3] * h_sh[k + 3];
        }
        float pre = gxv + ((a0 + a1) + (a2 + a3));
        gact[j] = (j >= 32 && j < 48) ? tanhfast(pre) : sigf(pre);
        __syncthreads();

        if (j < kHID) {
            float ig = gact[j];
            float fg = gact[kHID + j];
            float gg = gact[2 * kHID + j];
            float og = gact[3 * kHID + j];
            c_reg = fg * c_reg + ig * gg;
            h_reg = og * tanhfast(c_reg);
            h_sh[j] = h_reg;
        }
        __syncthreads();
    }
}

// ---------------------------------------------------------------------------
// Prep kernels. prepb applies the within-tile column permutation (permrow).
// ---------------------------------------------------------------------------
__global__ void prepb_kernel(const float* __restrict__ W_out) {
    int i = blockIdx.x * 256 + threadIdx.x;       // over kV*8 float4s
    float4 v = reinterpret_cast<const float4*>(W_out)[i];
    int n = i >> 3, j = i & 7;
    int rp = (n & ~127) + permrow(n & 127);       // permuted physical row
    uint32_t* dst = g_bbf + (size_t)rp * kFS;
    dst[fragcol(2 * j)]     = pack_bf16(v.x, v.y);
    dst[fragcol(2 * j + 1)] = pack_bf16(v.z, v.w);
}

__global__ void prepa_kernel() {
    int i = blockIdx.x * 256 + threadIdx.x;       // over kRows*8 float4s
    float4 v = reinterpret_cast<const float4*>(g_concat)[i];
    int r = i >> 3, j = i & 7;
    int c0 = fragcol(2 * j), c1 = fragcol(2 * j + 1);
    g_abf2[r * kFS + c0] = pack_bf16(v.x, v.y);
    g_abf2[r * kFS + c1] = pack_bf16(v.z, v.w);
    g_abf1[r * kFS + c0] = pack_bf16(v.x * kLOG2E, v.y * kLOG2E);
    g_abf1[r * kFS + c1] = pack_bf16(v.z * kLOG2E, v.w * kLOG2E);
}

// ---------------------------------------------------------------------------
// Kernel 2: bf16 tensor-core logits GEMM. Grid (250, 8). cp.async prefetch of
// B + 4 A tiles at CTA start; m-loop is wait/barrier/MMA only.
// Pass 1 (WRITE=false): 3 CTAs/SM (occupancy for MUFU/LDS latency hiding).
// Pass 2 (WRITE=true):  2 CTAs/SM, STG.128 direct fragment stores.
// ---------------------------------------------------------------------------
template <bool WRITE>
__global__ void __launch_bounds__(256, WRITE ? 2 : 3)
mma_pass(const float* __restrict__ b_out, float* __restrict__ out) {
    extern __shared__ uint32_t dynsm[];
    uint32_t* A_sm   = dynsm;                       // [4][3072]
    uint32_t* B_sm   = dynsm + 4 * kTileU32;        // [3072]
    float*    bias_sm = reinterpret_cast<float*>(dynsm + 5 * kTileU32);  // [128]
    float*    lz_sm   = bias_sm + kNT;              // [512]

    int tid  = threadIdx.x;
    int warp = tid >> 5;
    int lane = tid & 31;
    int tg   = lane & 3;
    int gr   = lane >> 2;
    int n0   = blockIdx.x * kNT;
    int mrow = warp * 16;
    int rbase = blockIdx.y * kMLoop * kMT;          // 512 rows per CTA

    // B tile: contiguous 12KB from g_bbf
    {
        uint32_t bdst = (uint32_t)__cvta_generic_to_shared(B_sm);
        const uint4* src = reinterpret_cast<const uint4*>(
            g_bbf + (size_t)n0 * kFS);
        for (int i = tid; i < kTileU32 / 4; i += 256)
            cp16(bdst + i * 16, src + i);
        CP_COMMIT();
    }
    // A tiles: 4 contiguous 12KB blocks
    const uint32_t* asrc_base = WRITE ? g_abf2 : g_abf1;
#pragma unroll
    for (int mi = 0; mi < kMLoop; ++mi) {
        uint32_t adst = (uint32_t)__cvta_generic_to_shared(A_sm + mi * kTileU32);
        const uint4* src = reinterpret_cast<const uint4*>(
            asrc_base + (size_t)(rbase + mi * kMT) * kFS);
        for (int i = tid; i < kTileU32 / 4; i += 256)
            cp16(adst + i * 16, src + i);
        CP_COMMIT();
    }
    // bias (PHYSICAL fragment order, matching permuted B) + lz
    if (tid < kNT) {
        int frag = tid >> 3, pos = tid & 7;
        int l = 16 * (frag >> 1) + 4 * (pos >> 1) + 2 * (frag & 1) + (pos & 1);
        float bv = b_out[n0 + l];
        bias_sm[tid] = WRITE ? bv : bv * kLOG2E;
    }
    if (WRITE) {
        for (int i = tid; i < kMLoop * kMT; i += 256)
            lz_sm[i] = g_lz[rbase + i];
    }

#pragma unroll
    for (int mi = 0; mi < kMLoop; ++mi) {
        switch (mi) {   // wait until B + A[0..mi] groups complete
            case 0:  CP_WAIT(3); break;
            case 1:  CP_WAIT(2); break;
            case 2:  CP_WAIT(1); break;
            default: CP_WAIT(0); break;
        }
        __syncthreads();

        int row0 = rbase + mi * kMT;
        const uint32_t* At = A_sm + mi * kTileU32;

        float c[16][4];
#pragma unroll
        for (int f = 0; f < 16; ++f) {
            float bx = bias_sm[f * 8 + tg * 2];
            float by = bias_sm[f * 8 + tg * 2 + 1];
            if (WRITE) {
                float z0 = lz_sm[mi * kMT + mrow + gr];
                float z1 = lz_sm[mi * kMT + mrow + gr + 8];
                c[f][0] = bx - z0; c[f][1] = by - z0;
                c[f][2] = bx - z1; c[f][3] = by - z1;
            } else {
                c[f][0] = bx; c[f][1] = by;
                c[f][2] = bx; c[f][3] = by;
            }
        }

        const uint32_t* ar0 = At + (mrow + gr) * kFS + tg * 2;
        const uint32_t* ar1 = At + (mrow + gr + 8) * kFS + tg * 2;
        uint2 alo0 = *reinterpret_cast<const uint2*>(ar0);
        uint2 alo1 = *reinterpret_cast<const uint2*>(ar1);
        uint2 ahi0 = *reinterpret_cast<const uint2*>(ar0 + 8);
        uint2 ahi1 = *reinterpret_cast<const uint2*>(ar1 + 8);
        const uint32_t* bp = B_sm + gr * kFS + tg * 2;

#pragma unroll
        for (int f = 0; f < 16; ++f) {
            uint2 blo = *reinterpret_cast<const uint2*>(bp + f * 8 * kFS);
            uint2 bhi = *reinterpret_cast<const uint2*>(bp + f * 8 * kFS + 8);
            mma_bf16(c[f], alo0.x, alo1.x, alo0.y, alo1.y, blo.x, blo.y);
            mma_bf16(c[f], ahi0.x, ahi1.x, ahi0.y, ahi1.y, bhi.x, bhi.y);
        }

        if (!WRITE) {
            float s0 = 0.f, s1 = 0.f;
#pragma unroll
            for (int f = 0; f < 16; ++f) {
                s0 += ex2f(c[f][0]) + ex2f(c[f][1]);
                s1 += ex2f(c[f][2]) + ex2f(c[f][3]);
            }
            s0 += __shfl_xor_sync(0xffffffffu, s0, 1);
            s0 += __shfl_xor_sync(0xffffffffu, s0, 2);
            s1 += __shfl_xor_sync(0xffffffffu, s1, 1);
            s1 += __shfl_xor_sync(0xffffffffu, s1, 2);
            if (tg == 0) {
                g_part[(size_t)blockIdx.x * kRows + row0 + mrow + gr]     = s0;
                g_part[(size_t)blockIdx.x * kRows + row0 + mrow + gr + 8] = s1;
            }
        } else {
            // STG.128: frag pair (2q,2q+1) slots = logical cols 16q+4tg..+3
            float* orow0 = out + (size_t)(row0 + mrow + gr) * kV + n0 + tg * 4;
            float* orow1 = orow0 + (size_t)8 * kV;
#pragma unroll
            for (int q = 0; q < 8; ++q) {
                __stcs(reinterpret_cast<float4*>(orow0 + q * 16),
                       make_float4(c[2 * q][0], c[2 * q][1],
                                   c[2 * q + 1][0], c[2 * q + 1][1]));
                __stcs(reinterpret_cast<float4*>(orow1 + q * 16),
                       make_float4(c[2 * q][2], c[2 * q][3],
                                   c[2 * q + 1][2], c[2 * q + 1][3]));
            }
        }
    }
}

// ---------------------------------------------------------------------------
// Kernel 3: logZ reduce. 256 blocks x 128 threads = 16 rows x 8 t-slices
// (fills all SMs); deterministic fixed-order combine.
// ---------------------------------------------------------------------------
__global__ void logz_kernel() {
    __shared__ float red[8][16];
    int rl    = threadIdx.x & 15;
    int slice = threadIdx.x >> 4;
    int row   = blockIdx.x * 16 + rl;

    float s = 0.f;
#pragma unroll 4
    for (int t = slice; t < kNTiles; t += 8)
        s += g_part[(size_t)t * kRows + row];
    red[slice][rl] = s;
    __syncthreads();

    if (threadIdx.x < 16) {
        float tot = 0.f;
#pragma unroll
        for (int i = 0; i < 8; ++i) tot += red[i][rl];
        g_lz[row] = __logf(tot);
    }
}

// ---------------------------------------------------------------------------
extern "C" void kernel_launch(void* const* d_in, const int* in_sizes, int n_in,
                              void* d_out, int out_size) {
    const int*   tokens = (const int*)d_in[0];
    const float* emb    = (const float*)d_in[1];
    const float* W_ih   = (const float*)d_in[2];
    const float* W_hh   = (const float*)d_in[3];
    const float* b_ih   = (const float*)d_in[4];
    const float* b_hh   = (const float*)d_in[5];
    const float* W_out  = (const float*)d_in[6];
    const float* b_out  = (const float*)d_in[7];
    const float* init_h = (const float*)d_in[8];
    const float* init_c = (const float*)d_in[9];
    float* out = (float*)d_out;

    static cudaStream_t s1 = nullptr;
    static cudaEvent_t evFork = nullptr, evB = nullptr;
    static bool attr_set = false;
    if (!attr_set) {
        cudaFuncSetAttribute(mma_pass<false>,
                             cudaFuncAttributeMaxDynamicSharedMemorySize,
                             kSmemBytes);
        cudaFuncSetAttribute(mma_pass<true>,
                             cudaFuncAttributeMaxDynamicSharedMemorySize,
                             kSmemBytes);
        cudaStreamCreateWithFlags(&s1, cudaStreamNonBlocking);
        cudaEventCreateWithFlags(&evFork, cudaEventDisableTiming);
        cudaEventCreateWithFlags(&evB, cudaEventDisableTiming);
        attr_set = true;
    }

    dim3 grid(kNTiles, kYBlk);

    // fork: prepb (depends only on W_out) overlaps gx+lstm+prepa
    cudaEventRecord(evFork, 0);
    cudaStreamWaitEvent(s1, evFork, 0);
    prepb_kernel<<<kV * 8 / 256, 256, 0, s1>>>(W_out);
    cudaEventRecord(evB, s1);

    gx_kernel<<<(kS * kB) / 4, 256>>>(tokens, emb, W_ih, b_ih, b_hh);
    lstm_kernel<<<32, 64>>>(W_hh, init_h, init_c);
    prepa_kernel<<<kRows * 8 / 256, 256>>>();
    cudaStreamWaitEvent(0, evB, 0);

    mma_pass<false><<<grid, 256, kSmemBytes>>>(b_out, out);
    logz_kernel<<<kRows / 16, 128>>>();
    mma_pass<true><<<grid, 256, kSmemBytes>>>(b_out, out);
}